// round 15
// baseline (speedup 1.0000x reference)
#include <cuda_runtime.h>
#include <cuda_fp16.h>
#include <cstdint>

#define BATCH   4096
#define T_STEPS 64
#define NDIM    128
#define HID     1024
#define DT_C    0.1f

// ---------------- device scratch (no allocations allowed) -------------------
__device__ float g_s [BATCH * NDIM];                    // fp32 exact state (CTA-private per G3 tile)
__device__ __align__(16) __half g_sr [BATCH * NDIM];    // fp16 state, A-tiled (K=128)
__device__ __align__(16) __half g_h1 [BATCH * HID];     // A-tiled (K=1024)
__device__ __align__(16) __half g_h2 [BATCH * HID];     // A-tiled (K=1024)
__device__ __align__(16) __half g_W1T[HID * NDIM];      // B-tiled N=1024,K=128
__device__ __align__(16) __half g_W2T[HID * HID];       // B-tiled N=1024,K=1024
__device__ __align__(16) __half g_W3T[256 * HID];       // B-tiled N=256,K=1024 (W3 cols 256..511)

// per-tile dependency counters (monotonic over steps; zeroed by init each replay)
__device__ unsigned g_c1[256];  // G1 tile (bm1*8+bn1) completions
__device__ unsigned g_c2[256];  // G2 tile (bm1*8+bn1) completions
__device__ unsigned g_c3[64];   // G3 64-row-block completions (4 per step)

// ---------------- helpers ----------------------------------------------------
__device__ __forceinline__ uint32_t smem_u32(const void* p) {
    uint32_t a;
    asm("{ .reg .u64 t; cvta.to.shared.u64 t, %1; cvt.u32.u64 %0, t; }" : "=r"(a) : "l"(p));
    return a;
}
__device__ __forceinline__ void cp16(uint32_t dst, const void* src) {
    asm volatile("cp.async.cg.shared.global [%0], [%1], 16;" :: "r"(dst), "l"(src));
}
__device__ __forceinline__ void cp_commit() { asm volatile("cp.async.commit_group;"); }
template<int N> __device__ __forceinline__ void cp_wait() {
    asm volatile("cp.async.wait_group %0;" :: "n"(N) : "memory");
}
__device__ __forceinline__ void spin_ge(unsigned* p, unsigned tgt) {
    if (tgt == 0u) return;
    volatile unsigned* vp = (volatile unsigned*)p;
    while (*vp < tgt) __nanosleep(50);
}

// mma.sync m16n8k16 fp16 in, fp32 acc: d += a*b  (512 MAC/cyc/SM legacy ceiling)
__device__ __forceinline__ void mma16(float (&d)[4], const uint32_t (&a)[4],
                                      const uint32_t (&b)[2]) {
    asm volatile(
        "mma.sync.aligned.m16n8k16.row.col.f32.f16.f16.f32 "
        "{%0,%1,%2,%3}, {%4,%5,%6,%7}, {%8,%9}, {%0,%1,%2,%3};"
        : "+f"(d[0]), "+f"(d[1]), "+f"(d[2]), "+f"(d[3])
        : "r"(a[0]), "r"(a[1]), "r"(a[2]), "r"(a[3]), "r"(b[0]), "r"(b[1]));
}

// Fragment-native tiled layouts (half element index).
__device__ __forceinline__ size_t a_idx_h(int m, int k, int K) {
    return ((size_t)(m >> 4) * (K >> 4) + (k >> 4)) * 256
         + (((m & 7) * 4 + ((k & 7) >> 1)) << 3)
         + ((((m >> 3) & 1) | (((k >> 3) & 1) << 1)) << 1) + (k & 1);
}
__device__ __forceinline__ size_t b_idx_h(int n, int k, int K) {
    return ((size_t)(n >> 3) * (K >> 4) + (k >> 4)) * 128
         + (((n & 7) * 4 + ((k & 7) >> 1)) << 2)
         + (((k >> 3) & 1) << 1) + (k & 1);
}

// ---------------------------------------------------------------------------
__global__ void init_kernel(const float* __restrict__ states, float* __restrict__ out) {
    int i = blockIdx.x * blockDim.x + threadIdx.x;
    if (i < 256) g_c1[i] = 0u;
    else if (i < 512) g_c2[i - 256] = 0u;
    else if (i < 576) g_c3[i - 512] = 0u;
    if (i < BATCH * NDIM) {
        int b = i >> 7, n = i & 127;
        float v = states[(size_t)b * T_STEPS * NDIM + n];
        g_s[i] = v;
        g_sr[a_idx_h(b, n, NDIM)] = __float2half_rn(v);
        out[((size_t)b * (T_STEPS + 1)) * NDIM + n] = v;
    }
}

__global__ void prep_all(const float* __restrict__ W1, const float* __restrict__ W2,
                         const float* __restrict__ W3,
                         __half* __restrict__ w1t, __half* __restrict__ w2t,
                         __half* __restrict__ w3t) {
    int idx = blockIdx.x * blockDim.x + threadIdx.x;
    const int NW2 = 1024 * 1024, NW3 = 256 * 1024, NW1 = 1024 * 128;
    if (idx < NW2) {
        int n = idx & 1023, k = idx >> 10;
        w2t[b_idx_h(n, k, 1024)] = __float2half_rn(W2[(size_t)k * 1024 + n]);
    } else if (idx < NW2 + NW3) {
        int r = idx - NW2;
        int n = r & 255, k = r >> 8;
        w3t[b_idx_h(n, k, 1024)] = __float2half_rn(W3[(size_t)k * 512 + 256 + n]);
    } else if (idx < NW2 + NW3 + NW1) {
        int r = idx - NW2 - NW3;
        int n = r & 1023, k = r >> 10;
        w1t[b_idx_h(n, k, 128)] = __float2half_rn(W1[(size_t)k * 1024 + n]);
    }
}

// ---------------------------------------------------------------------------
// Persistent rollout: 256 CTAs x 128 threads run all 64 steps.
// Static B operands + actions pre-issued BEFORE each spin (DMA overlaps poll);
// fine-grained per-tile waits let consumers start on the first ready tile.
// hS float offsets: 0 b1 | 128 b2 | 256 b3 | 320 w0 | 448 w1 |
//                   576 a0G1 | 704 a1G1 | 832 a0G3 | 896 a1G3
// ---------------------------------------------------------------------------
__global__ void __launch_bounds__(128, 2)
rollout(const float* __restrict__ b1, const float* __restrict__ b2,
        const float* __restrict__ b3p, const float* __restrict__ W1raw,
        const float* __restrict__ actions, float* __restrict__ out)
{
    constexpr int OFF = 4096;
    extern __shared__ char smem[];
    float* hS = (float*)smem;
    const uint32_t sb = smem_u32(smem);
    const int tid = threadIdx.x, lane = tid & 31, warp = tid >> 5;
    const int wm = warp & 1, wn = warp >> 1;
    const int cta = blockIdx.x;
    const int bm1 = cta >> 3, bn1 = cta & 7;     // G1/G2 tile
    const int bm3 = cta >> 2, bn3 = cta & 3;     // G3 tile
    const int r = lane >> 2, tig = lane & 3;
    const int KOUT = HID >> 4;                   // 64

    // static header
    hS[tid]       = b1[bn1 * 128 + tid];
    hS[128 + tid] = b2[bn1 * 128 + tid];
    if (tid < 64) hS[256 + tid] = b3p[bn3 * 64 + tid];
    hS[320 + tid] = W1raw[(size_t)128 * HID + bn1 * 128 + tid];
    hS[448 + tid] = W1raw[(size_t)129 * HID + bn1 * 128 + tid];

    for (int t = 0; t < T_STEPS; t++) {
        // ================= G1 =================
        // pre-issue static B (W1T) for all 4 stages + actions, then spin
        #pragma unroll
        for (int ks = 0; ks < 4; ks++) {
            uint32_t sB = sb + OFF + (uint32_t)ks * 16384 + 8192;
            #pragma unroll
            for (int v = tid; v < 512; v += 128) {
                int j = v >> 5, inner = v & 31;
                cp16(sB + (uint32_t)v * 16,
                     g_W1T + ((size_t)(bn1 * 16 + j) * 8 + 2 * ks) * 128 + inner * 8);
            }
        }
        {
            int m = bm1 * 128 + tid;
            const float* ap = actions + ((size_t)m * T_STEPS + t) * 2;
            hS[576 + tid] = ap[0];
            hS[704 + tid] = ap[1];
        }
        if (tid == 0) {
            spin_ge(&g_c3[2 * bm1],     4u * (unsigned)t);
            spin_ge(&g_c3[2 * bm1 + 1], 4u * (unsigned)t);
            __threadfence();
        }
        __syncthreads();
        {
            // dependent A loads (g_sr)
            #pragma unroll
            for (int ks = 0; ks < 4; ks++) {
                uint32_t sa = sb + OFF + (uint32_t)ks * 16384;
                #pragma unroll
                for (int v = tid; v < 512; v += 128) {
                    int i = v >> 6, inner = v & 63;
                    cp16(sa + (uint32_t)v * 16,
                         g_sr + ((size_t)(bm1 * 8 + i) * 8 + 2 * ks) * 256 + inner * 8);
                }
            }
            cp_commit();
            cp_wait<0>();
            __syncthreads();

            float acc[4][8][4];
            #pragma unroll
            for (int i = 0; i < 4; i++)
                #pragma unroll
                for (int j = 0; j < 8; j++)
                    #pragma unroll
                    for (int q = 0; q < 4; q++) acc[i][j][q] = 0.f;

            #pragma unroll
            for (int kt = 0; kt < 4; kt++) {
                uint32_t sa = sb + OFF + (uint32_t)kt * 16384;
                uint32_t sB = sa + 8192;
                #pragma unroll
                for (int kk = 0; kk < 2; kk++) {
                    uint32_t afr[4][4], bfr[8][2];
                    #pragma unroll
                    for (int mf = 0; mf < 4; mf++) {
                        uint32_t ad = sa + (uint32_t)((wm * 4 + mf) * 1024 + kk * 512) + lane * 16;
                        asm volatile("ld.shared.v4.b32 {%0,%1,%2,%3}, [%4];"
                            : "=r"(afr[mf][0]), "=r"(afr[mf][1]), "=r"(afr[mf][2]), "=r"(afr[mf][3])
                            : "r"(ad));
                    }
                    #pragma unroll
                    for (int nf = 0; nf < 8; nf++) {
                        uint32_t bd = sB + (uint32_t)((wn * 8 + nf) * 512 + kk * 256) + lane * 8;
                        asm volatile("ld.shared.v2.b32 {%0,%1}, [%2];"
                            : "=r"(bfr[nf][0]), "=r"(bfr[nf][1]) : "r"(bd));
                    }
                    #pragma unroll
                    for (int mf = 0; mf < 4; mf++)
                        #pragma unroll
                        for (int nf = 0; nf < 8; nf++)
                            mma16(acc[mf][nf], afr[mf], bfr[nf]);
                }
            }

            #pragma unroll
            for (int mf = 0; mf < 4; mf++) {
                int ml = wm * 64 + mf * 16 + r;
                float a0L = hS[576 + ml],     a1L = hS[704 + ml];
                float a0H = hS[576 + ml + 8], a1H = hS[704 + ml + 8];
                #pragma unroll
                for (int nfp = 0; nfp < 4; nfp++) {
                    uint32_t q[4];
                    #pragma unroll
                    for (int h = 0; h < 2; h++) {
                        int nf = nfp * 2 + h;
                        int nl0 = wn * 64 + nf * 8 + tig * 2;
                        float v00 = acc[mf][nf][0] + hS[nl0];
                        float v01 = acc[mf][nf][1] + hS[nl0 + 1];
                        float v10 = acc[mf][nf][2] + hS[nl0];
                        float v11 = acc[mf][nf][3] + hS[nl0 + 1];
                        v00 += a0L * hS[320 + nl0]     + a1L * hS[448 + nl0];
                        v01 += a0L * hS[320 + nl0 + 1] + a1L * hS[448 + nl0 + 1];
                        v10 += a0H * hS[320 + nl0]     + a1H * hS[448 + nl0];
                        v11 += a0H * hS[320 + nl0 + 1] + a1H * hS[448 + nl0 + 1];
                        v00 = v00 > 0.f ? v00 : 0.f;  v01 = v01 > 0.f ? v01 : 0.f;
                        v10 = v10 > 0.f ? v10 : 0.f;  v11 = v11 > 0.f ? v11 : 0.f;
                        __half2 lo = __floats2half2_rn(v00, v01);
                        __half2 hi = __floats2half2_rn(v10, v11);
                        q[h * 2]     = *(uint32_t*)&lo;
                        q[h * 2 + 1] = *(uint32_t*)&hi;
                    }
                    int mblk = (bm1 * 128 + ml) >> 4;
                    int nblk = (bn1 * 128 + wn * 64 + nfp * 16) >> 4;
                    size_t off = ((size_t)mblk * KOUT + nblk) * 256 + lane * 8;
                    *(uint4*)&g_h1[off] = make_uint4(q[0], q[1], q[2], q[3]);
                }
            }
        }
        __threadfence();
        __syncthreads();
        if (tid == 0) atomicAdd(&g_c1[cta], 1u);

        // ================= G2 =================
        {
            constexpr int STAGE = 16384;
            constexpr int KT = 32;
            auto loadA = [&](int ks) {
                uint32_t sa = sb + OFF + (uint32_t)(ks & 3) * STAGE;
                #pragma unroll
                for (int v = tid; v < 512; v += 128) {
                    int i = v >> 6, inner = v & 63;
                    cp16(sa + (uint32_t)v * 16,
                         g_h1 + ((size_t)(bm1 * 8 + i) * 64 + 2 * ks) * 256 + inner * 8);
                }
            };
            auto loadB = [&](int ks) {
                uint32_t sB = sb + OFF + (uint32_t)(ks & 3) * STAGE + 8192;
                #pragma unroll
                for (int v = tid; v < 512; v += 128) {
                    int j = v >> 5, inner = v & 31;
                    cp16(sB + (uint32_t)v * 16,
                         g_W2T + ((size_t)(bn1 * 16 + j) * 64 + 2 * ks) * 128 + inner * 8);
                }
            };

            // pre-issue static B stages 0-2 (uncommitted), then spin on tile 0
            loadB(0); loadB(1); loadB(2);
            if (tid == 0) { spin_ge(&g_c1[bm1 * 8 + 0], (unsigned)(t + 1)); __threadfence(); }
            __syncthreads();
            loadA(0); cp_commit();     // group0 = B0,B1,B2,A0
            loadA(1); cp_commit();     // group1 = A1
            loadA(2); cp_commit();     // group2 = A2

            float acc[4][8][4];
            #pragma unroll
            for (int i = 0; i < 4; i++)
                #pragma unroll
                for (int j = 0; j < 8; j++)
                    #pragma unroll
                    for (int q = 0; q < 4; q++) acc[i][j][q] = 0.f;

            for (int kt = 0; kt < KT; kt++) {
                int ahead = KT - 1 - kt;
                if (ahead >= 2) cp_wait<2>();
                else if (ahead == 1) cp_wait<1>();
                else cp_wait<0>();
                int s = kt + 3;
                if (tid == 0 && s < KT && (s & 3) == 0) {
                    spin_ge(&g_c1[bm1 * 8 + (s >> 2)], (unsigned)(t + 1));
                    __threadfence();
                }
                __syncthreads();
                if (s < KT) { loadA(s); loadB(s); cp_commit(); }

                uint32_t sa = sb + OFF + (uint32_t)(kt & 3) * STAGE;
                uint32_t sB = sa + 8192;
                #pragma unroll
                for (int kk = 0; kk < 2; kk++) {
                    uint32_t afr[4][4], bfr[8][2];
                    #pragma unroll
                    for (int mf = 0; mf < 4; mf++) {
                        uint32_t ad = sa + (uint32_t)((wm * 4 + mf) * 1024 + kk * 512) + lane * 16;
                        asm volatile("ld.shared.v4.b32 {%0,%1,%2,%3}, [%4];"
                            : "=r"(afr[mf][0]), "=r"(afr[mf][1]), "=r"(afr[mf][2]), "=r"(afr[mf][3])
                            : "r"(ad));
                    }
                    #pragma unroll
                    for (int nf = 0; nf < 8; nf++) {
                        uint32_t bd = sB + (uint32_t)((wn * 8 + nf) * 512 + kk * 256) + lane * 8;
                        asm volatile("ld.shared.v2.b32 {%0,%1}, [%2];"
                            : "=r"(bfr[nf][0]), "=r"(bfr[nf][1]) : "r"(bd));
                    }
                    #pragma unroll
                    for (int mf = 0; mf < 4; mf++)
                        #pragma unroll
                        for (int nf = 0; nf < 8; nf++)
                            mma16(acc[mf][nf], afr[mf], bfr[nf]);
                }
            }

            #pragma unroll
            for (int mf = 0; mf < 4; mf++) {
                int ml = wm * 64 + mf * 16 + r;
                #pragma unroll
                for (int nfp = 0; nfp < 4; nfp++) {
                    uint32_t q[4];
                    #pragma unroll
                    for (int h = 0; h < 2; h++) {
                        int nf = nfp * 2 + h;
                        int nl0 = wn * 64 + nf * 8 + tig * 2;
                        float v00 = acc[mf][nf][0] + hS[128 + nl0];
                        float v01 = acc[mf][nf][1] + hS[128 + nl0 + 1];
                        float v10 = acc[mf][nf][2] + hS[128 + nl0];
                        float v11 = acc[mf][nf][3] + hS[128 + nl0 + 1];
                        v00 = v00 > 0.f ? v00 : 0.f;  v01 = v01 > 0.f ? v01 : 0.f;
                        v10 = v10 > 0.f ? v10 : 0.f;  v11 = v11 > 0.f ? v11 : 0.f;
                        __half2 lo = __floats2half2_rn(v00, v01);
                        __half2 hi = __floats2half2_rn(v10, v11);
                        q[h * 2]     = *(uint32_t*)&lo;
                        q[h * 2 + 1] = *(uint32_t*)&hi;
                    }
                    int mblk = (bm1 * 128 + ml) >> 4;
                    int nblk = (bn1 * 128 + wn * 64 + nfp * 16) >> 4;
                    size_t off = ((size_t)mblk * KOUT + nblk) * 256 + lane * 8;
                    *(uint4*)&g_h2[off] = make_uint4(q[0], q[1], q[2], q[3]);
                }
            }
        }
        __threadfence();
        __syncthreads();
        if (tid == 0) atomicAdd(&g_c2[cta], 1u);

        // ================= G3 =================
        {
            constexpr int STAGE = 8192;
            constexpr int KT = 32;
            const int cbase = (bm3 >> 1) * 8;
            auto loadA = [&](int ks) {
                uint32_t sa = sb + OFF + (uint32_t)(ks & 3) * STAGE;
                #pragma unroll
                for (int v = tid; v < 256; v += 128) {
                    int i = v >> 6, inner = v & 63;
                    cp16(sa + (uint32_t)v * 16,
                         g_h2 + ((size_t)(bm3 * 4 + i) * 64 + 2 * ks) * 256 + inner * 8);
                }
            };
            auto loadB = [&](int ks) {
                uint32_t sB = sb + OFF + (uint32_t)(ks & 3) * STAGE + 4096;
                #pragma unroll
                for (int v = tid; v < 256; v += 128) {
                    int j = v >> 5, inner = v & 31;
                    cp16(sB + (uint32_t)v * 16,
                         g_W3T + ((size_t)(bn3 * 8 + j) * 64 + 2 * ks) * 128 + inner * 8);
                }
            };

            loadB(0); loadB(1); loadB(2);
            if (tid < 64) {
                int m = bm3 * 64 + tid;
                const float* ap = actions + ((size_t)m * T_STEPS + t) * 2;
                hS[832 + tid] = ap[0];
                hS[896 + tid] = ap[1];
            }
            if (tid == 0) { spin_ge(&g_c2[cbase + 0], (unsigned)(t + 1)); __threadfence(); }
            __syncthreads();
            loadA(0); cp_commit();
            loadA(1); cp_commit();
            loadA(2); cp_commit();

            float acc[2][4][4];
            #pragma unroll
            for (int i = 0; i < 2; i++)
                #pragma unroll
                for (int j = 0; j < 4; j++)
                    #pragma unroll
                    for (int q = 0; q < 4; q++) acc[i][j][q] = 0.f;

            for (int kt = 0; kt < KT; kt++) {
                int ahead = KT - 1 - kt;
                if (ahead >= 2) cp_wait<2>();
                else if (ahead == 1) cp_wait<1>();
                else cp_wait<0>();
                int s = kt + 3;
                if (tid == 0 && s < KT && (s & 3) == 0) {
                    spin_ge(&g_c2[cbase + (s >> 2)], (unsigned)(t + 1));
                    __threadfence();
                }
                __syncthreads();
                if (s < KT) { loadA(s); loadB(s); cp_commit(); }

                uint32_t sa = sb + OFF + (uint32_t)(kt & 3) * STAGE;
                uint32_t sB = sa + 4096;
                #pragma unroll
                for (int kk = 0; kk < 2; kk++) {
                    uint32_t afr[2][4], bfr[4][2];
                    #pragma unroll
                    for (int mf = 0; mf < 2; mf++) {
                        uint32_t ad = sa + (uint32_t)((wm * 2 + mf) * 1024 + kk * 512) + lane * 16;
                        asm volatile("ld.shared.v4.b32 {%0,%1,%2,%3}, [%4];"
                            : "=r"(afr[mf][0]), "=r"(afr[mf][1]), "=r"(afr[mf][2]), "=r"(afr[mf][3])
                            : "r"(ad));
                    }
                    #pragma unroll
                    for (int nf = 0; nf < 4; nf++) {
                        uint32_t bd = sB + (uint32_t)((wn * 4 + nf) * 512 + kk * 256) + lane * 8;
                        asm volatile("ld.shared.v2.b32 {%0,%1}, [%2];"
                            : "=r"(bfr[nf][0]), "=r"(bfr[nf][1]) : "r"(bd));
                    }
                    #pragma unroll
                    for (int mf = 0; mf < 2; mf++)
                        #pragma unroll
                        for (int nf = 0; nf < 4; nf++)
                            mma16(acc[mf][nf], afr[mf], bfr[nf]);
                }
            }

            #pragma unroll
            for (int mf = 0; mf < 2; mf++) {
                int ml = wm * 32 + mf * 16 + r;
                int m = bm3 * 64 + ml;
                float a0L = hS[832 + ml],     a1L = hS[896 + ml];
                float a0H = hS[832 + ml + 8], a1H = hS[896 + ml + 8];
                #pragma unroll
                for (int nf = 0; nf < 4; nf++) {
                    int nl0 = wn * 32 + nf * 8 + tig * 2;
                    int n = bn3 * 32 + (nl0 >> 1);
                    float p0 = acc[mf][nf][0] + hS[256 + nl0];
                    float p1 = acc[mf][nf][1] + hS[256 + nl0 + 1];
                    float p2 = acc[mf][nf][2] + hS[256 + nl0];
                    float p3 = acc[mf][nf][3] + hS[256 + nl0 + 1];
                    float sv0 = g_s[(size_t)m * NDIM + n];
                    float sv1 = g_s[(size_t)(m + 8) * NDIM + n];
                    float ns0 = fmaf(DT_C, fmaf(p0, a0L, p1 * a1L), sv0);
                    float ns1 = fmaf(DT_C, fmaf(p2, a0H, p3 * a1H), sv1);
                    g_s[(size_t)m * NDIM + n] = ns0;
                    g_s[(size_t)(m + 8) * NDIM + n] = ns1;
                    g_sr[a_idx_h(m, n, NDIM)] = __float2half_rn(ns0);
                    g_sr[a_idx_h(m + 8, n, NDIM)] = __float2half_rn(ns1);
                    out[((size_t)m * (T_STEPS + 1) + t + 1) * NDIM + n] = ns0;
                    out[((size_t)(m + 8) * (T_STEPS + 1) + t + 1) * NDIM + n] = ns1;
                }
            }
        }
        __threadfence();
        __syncthreads();
        if (tid == 0) atomicAdd(&g_c3[bm3], 1u);
    }
}

// ---------------------------------------------------------------------------
extern "C" void kernel_launch(void* const* d_in, const int* in_sizes, int n_in,
                              void* d_out, int out_size) {
    const float* states  = (const float*)d_in[0];
    const float* actions = (const float*)d_in[1];
    const float* W1 = (const float*)d_in[2];
    const float* b1 = (const float*)d_in[3];
    const float* W2 = (const float*)d_in[4];
    const float* b2 = (const float*)d_in[5];
    const float* W3 = (const float*)d_in[6];
    const float* b3 = (const float*)d_in[7];
    float* out = (float*)d_out;

    __half *pw1t, *pw2t, *pw3t;
    cudaGetSymbolAddress((void**)&pw1t, g_W1T);
    cudaGetSymbolAddress((void**)&pw2t, g_W2T);
    cudaGetSymbolAddress((void**)&pw3t, g_W3T);

    const int SMEM = 4096 + 4 * 16384;   // 69632
    cudaFuncSetAttribute((const void*)rollout,
                         cudaFuncAttributeMaxDynamicSharedMemorySize, SMEM);

    init_kernel<<<(BATCH * NDIM + 255) / 256, 256>>>(states, out);
    const int PREP_N = 1024 * 1024 + 256 * 1024 + 1024 * 128;
    prep_all<<<(PREP_N + 255) / 256, 256>>>(W1, W2, W3, pw1t, pw2t, pw3t);

    rollout<<<256, 128, SMEM>>>(b1, b2, b3 + 256, W1, actions, out);
}

// round 16
// speedup vs baseline: 1.2463x; 1.2463x over previous
#include <cuda_runtime.h>
#include <cuda_fp16.h>
#include <cstdint>

#define BATCH   4096
#define T_STEPS 64
#define NDIM    128
#define HID     1024
#define DT_C    0.1f

// ---------------- device scratch (no allocations allowed) -------------------
__device__ float g_s [BATCH * NDIM];                    // fp32 exact state (CTA-private per G3 tile)
__device__ __align__(16) __half g_sr [BATCH * NDIM];    // fp16 state, A-tiled (K=128)
__device__ __align__(16) __half g_h1 [BATCH * HID];     // A-tiled (K=1024)
__device__ __align__(16) __half g_h2 [BATCH * HID];     // A-tiled (K=1024)
__device__ __align__(16) __half g_W1T[HID * NDIM];      // B-tiled N=1024,K=128
__device__ __align__(16) __half g_W2T[HID * HID];       // B-tiled N=1024,K=1024
__device__ __align__(16) __half g_W3T[256 * HID];       // B-tiled N=256,K=1024 (W3 cols 256..511)

// dependency counters (monotonic across the 64 steps; zeroed by init each replay)
__device__ unsigned g_c1[32];   // G1 row-block completion (8 per step)
__device__ unsigned g_c2[32];   // G2 row-block completion (8 per step)
__device__ unsigned g_c3[64];   // G3 64-row-block completion (4 per step)

// ---------------- helpers ----------------------------------------------------
__device__ __forceinline__ uint32_t smem_u32(const void* p) {
    uint32_t a;
    asm("{ .reg .u64 t; cvta.to.shared.u64 t, %1; cvt.u32.u64 %0, t; }" : "=r"(a) : "l"(p));
    return a;
}
__device__ __forceinline__ void cp16(uint32_t dst, const void* src) {
    asm volatile("cp.async.cg.shared.global [%0], [%1], 16;" :: "r"(dst), "l"(src));
}
__device__ __forceinline__ void cp_commit() { asm volatile("cp.async.commit_group;"); }
template<int N> __device__ __forceinline__ void cp_wait() {
    asm volatile("cp.async.wait_group %0;" :: "n"(N) : "memory");
}
__device__ __forceinline__ void spin_ge(unsigned* p, unsigned tgt) {
    if (tgt == 0u) return;
    volatile unsigned* vp = (volatile unsigned*)p;
    while (*vp < tgt) __nanosleep(50);
}

// mma.sync m16n8k16 fp16 in, fp32 acc: d += a*b  (512 MAC/cyc/SM legacy ceiling)
__device__ __forceinline__ void mma16(float (&d)[4], const uint32_t (&a)[4],
                                      const uint32_t (&b)[2]) {
    asm volatile(
        "mma.sync.aligned.m16n8k16.row.col.f32.f16.f16.f32 "
        "{%0,%1,%2,%3}, {%4,%5,%6,%7}, {%8,%9}, {%0,%1,%2,%3};"
        : "+f"(d[0]), "+f"(d[1]), "+f"(d[2]), "+f"(d[3])
        : "r"(a[0]), "r"(a[1]), "r"(a[2]), "r"(a[3]), "r"(b[0]), "r"(b[1]));
}

// Fragment-native tiled layouts (half element index).
__device__ __forceinline__ size_t a_idx_h(int m, int k, int K) {
    return ((size_t)(m >> 4) * (K >> 4) + (k >> 4)) * 256
         + (((m & 7) * 4 + ((k & 7) >> 1)) << 3)
         + ((((m >> 3) & 1) | (((k >> 3) & 1) << 1)) << 1) + (k & 1);
}
__device__ __forceinline__ size_t b_idx_h(int n, int k, int K) {
    return ((size_t)(n >> 3) * (K >> 4) + (k >> 4)) * 128
         + (((n & 7) * 4 + ((k & 7) >> 1)) << 2)
         + (((k >> 3) & 1) << 1) + (k & 1);
}

// ---------------------------------------------------------------------------
__global__ void init_kernel(const float* __restrict__ states, float* __restrict__ out) {
    int i = blockIdx.x * blockDim.x + threadIdx.x;
    if (i < 32) g_c1[i] = 0u;
    else if (i < 64) g_c2[i - 32] = 0u;
    else if (i < 128) g_c3[i - 64] = 0u;
    if (i < BATCH * NDIM) {
        int b = i >> 7, n = i & 127;
        float v = states[(size_t)b * T_STEPS * NDIM + n];
        g_s[i] = v;
        g_sr[a_idx_h(b, n, NDIM)] = __float2half_rn(v);
        out[((size_t)b * (T_STEPS + 1)) * NDIM + n] = v;
    }
}

__global__ void prep_all(const float* __restrict__ W1, const float* __restrict__ W2,
                         const float* __restrict__ W3,
                         __half* __restrict__ w1t, __half* __restrict__ w2t,
                         __half* __restrict__ w3t) {
    int idx = blockIdx.x * blockDim.x + threadIdx.x;
    const int NW2 = 1024 * 1024, NW3 = 256 * 1024, NW1 = 1024 * 128;
    if (idx < NW2) {
        int n = idx & 1023, k = idx >> 10;
        w2t[b_idx_h(n, k, 1024)] = __float2half_rn(W2[(size_t)k * 1024 + n]);
    } else if (idx < NW2 + NW3) {
        int r = idx - NW2;
        int n = r & 255, k = r >> 8;
        w3t[b_idx_h(n, k, 1024)] = __float2half_rn(W3[(size_t)k * 512 + 256 + n]);
    } else if (idx < NW2 + NW3 + NW1) {
        int r = idx - NW2 - NW3;
        int n = r & 1023, k = r >> 10;
        w1t[b_idx_h(n, k, 128)] = __float2half_rn(W1[(size_t)k * 1024 + n]);
    }
}

// ---------------------------------------------------------------------------
// Persistent rollout (R14 structure): 256 CTAs x 128 threads, 64 steps.
// R16 delta vs R14: G1 pre-issues its step-invariant W1T cp.asyncs + action
// smem writes BEFORE the spin (DMA overlaps the poll). G2/G3 keep the single
// coarse wait OUTSIDE their pipelines (R15 showed in-pipeline spins poison it).
// hS float offsets: 0 b1 | 128 b2 | 256 b3 | 320 w0 | 448 w1 |
//                   576 a0G1 | 704 a1G1 | 832 a0G3 | 896 a1G3
// ---------------------------------------------------------------------------
__global__ void __launch_bounds__(128, 2)
rollout(const float* __restrict__ b1, const float* __restrict__ b2,
        const float* __restrict__ b3p, const float* __restrict__ W1raw,
        const float* __restrict__ actions, float* __restrict__ out)
{
    constexpr int OFF = 4096;
    extern __shared__ char smem[];
    float* hS = (float*)smem;
    const uint32_t sb = smem_u32(smem);
    const int tid = threadIdx.x, lane = tid & 31, warp = tid >> 5;
    const int wm = warp & 1, wn = warp >> 1;
    const int cta = blockIdx.x;
    const int bm1 = cta >> 3, bn1 = cta & 7;     // G1/G2 tile
    const int bm3 = cta >> 2, bn3 = cta & 3;     // G3 tile
    const int r = lane >> 2, tig = lane & 3;
    const int KOUT = HID >> 4;                   // 64

    // static header
    hS[tid]       = b1[bn1 * 128 + tid];
    hS[128 + tid] = b2[bn1 * 128 + tid];
    if (tid < 64) hS[256 + tid] = b3p[bn3 * 64 + tid];
    hS[320 + tid] = W1raw[(size_t)128 * HID + bn1 * 128 + tid];
    hS[448 + tid] = W1raw[(size_t)129 * HID + bn1 * 128 + tid];

    for (int t = 0; t < T_STEPS; t++) {
        // ================= G1 =================
        // pre-issue step-invariant B (W1T, uncommitted) + actions, THEN spin
        #pragma unroll
        for (int ks = 0; ks < 4; ks++) {
            uint32_t sB = sb + OFF + (uint32_t)ks * 16384 + 8192;
            #pragma unroll
            for (int v = tid; v < 512; v += 128) {
                int j = v >> 5, inner = v & 31;
                cp16(sB + (uint32_t)v * 16,
                     g_W1T + ((size_t)(bn1 * 16 + j) * 8 + 2 * ks) * 128 + inner * 8);
            }
        }
        {
            int m = bm1 * 128 + tid;
            const float* ap = actions + ((size_t)m * T_STEPS + t) * 2;
            hS[576 + tid] = ap[0];
            hS[704 + tid] = ap[1];
        }
        if (tid == 0) {
            spin_ge(&g_c3[2 * bm1],     4u * (unsigned)t);
            spin_ge(&g_c3[2 * bm1 + 1], 4u * (unsigned)t);
            __threadfence();
        }
        __syncthreads();
        {
            // dependent A loads (g_sr); single commit covers pre-issued B too
            #pragma unroll
            for (int ks = 0; ks < 4; ks++) {
                uint32_t sa = sb + OFF + (uint32_t)ks * 16384;
                #pragma unroll
                for (int v = tid; v < 512; v += 128) {
                    int i = v >> 6, inner = v & 63;
                    cp16(sa + (uint32_t)v * 16,
                         g_sr + ((size_t)(bm1 * 8 + i) * 8 + 2 * ks) * 256 + inner * 8);
                }
            }
            cp_commit();
            cp_wait<0>();
            __syncthreads();

            float acc[4][8][4];
            #pragma unroll
            for (int i = 0; i < 4; i++)
                #pragma unroll
                for (int j = 0; j < 8; j++)
                    #pragma unroll
                    for (int q = 0; q < 4; q++) acc[i][j][q] = 0.f;

            #pragma unroll
            for (int kt = 0; kt < 4; kt++) {
                uint32_t sa = sb + OFF + (uint32_t)kt * 16384;
                uint32_t sB = sa + 8192;
                #pragma unroll
                for (int kk = 0; kk < 2; kk++) {
                    uint32_t afr[4][4], bfr[8][2];
                    #pragma unroll
                    for (int mf = 0; mf < 4; mf++) {
                        uint32_t ad = sa + (uint32_t)((wm * 4 + mf) * 1024 + kk * 512) + lane * 16;
                        asm volatile("ld.shared.v4.b32 {%0,%1,%2,%3}, [%4];"
                            : "=r"(afr[mf][0]), "=r"(afr[mf][1]), "=r"(afr[mf][2]), "=r"(afr[mf][3])
                            : "r"(ad));
                    }
                    #pragma unroll
                    for (int nf = 0; nf < 8; nf++) {
                        uint32_t bd = sB + (uint32_t)((wn * 8 + nf) * 512 + kk * 256) + lane * 8;
                        asm volatile("ld.shared.v2.b32 {%0,%1}, [%2];"
                            : "=r"(bfr[nf][0]), "=r"(bfr[nf][1]) : "r"(bd));
                    }
                    #pragma unroll
                    for (int mf = 0; mf < 4; mf++)
                        #pragma unroll
                        for (int nf = 0; nf < 8; nf++)
                            mma16(acc[mf][nf], afr[mf], bfr[nf]);
                }
            }

            #pragma unroll
            for (int mf = 0; mf < 4; mf++) {
                int ml = wm * 64 + mf * 16 + r;
                float a0L = hS[576 + ml],     a1L = hS[704 + ml];
                float a0H = hS[576 + ml + 8], a1H = hS[704 + ml + 8];
                #pragma unroll
                for (int nfp = 0; nfp < 4; nfp++) {
                    uint32_t q[4];
                    #pragma unroll
                    for (int h = 0; h < 2; h++) {
                        int nf = nfp * 2 + h;
                        int nl0 = wn * 64 + nf * 8 + tig * 2;
                        float v00 = acc[mf][nf][0] + hS[nl0];
                        float v01 = acc[mf][nf][1] + hS[nl0 + 1];
                        float v10 = acc[mf][nf][2] + hS[nl0];
                        float v11 = acc[mf][nf][3] + hS[nl0 + 1];
                        v00 += a0L * hS[320 + nl0]     + a1L * hS[448 + nl0];
                        v01 += a0L * hS[320 + nl0 + 1] + a1L * hS[448 + nl0 + 1];
                        v10 += a0H * hS[320 + nl0]     + a1H * hS[448 + nl0];
                        v11 += a0H * hS[320 + nl0 + 1] + a1H * hS[448 + nl0 + 1];
                        v00 = v00 > 0.f ? v00 : 0.f;  v01 = v01 > 0.f ? v01 : 0.f;
                        v10 = v10 > 0.f ? v10 : 0.f;  v11 = v11 > 0.f ? v11 : 0.f;
                        __half2 lo = __floats2half2_rn(v00, v01);
                        __half2 hi = __floats2half2_rn(v10, v11);
                        q[h * 2]     = *(uint32_t*)&lo;
                        q[h * 2 + 1] = *(uint32_t*)&hi;
                    }
                    int mblk = (bm1 * 128 + ml) >> 4;
                    int nblk = (bn1 * 128 + wn * 64 + nfp * 16) >> 4;
                    size_t off = ((size_t)mblk * KOUT + nblk) * 256 + lane * 8;
                    *(uint4*)&g_h1[off] = make_uint4(q[0], q[1], q[2], q[3]);
                }
            }
        }
        __threadfence();
        __syncthreads();
        if (tid == 0) atomicAdd(&g_c1[bm1], 1u);

        // ================= G2 ================= (R14 verbatim)
        if (tid == 0) { spin_ge(&g_c1[bm1], 8u * (unsigned)(t + 1)); __threadfence(); }
        __syncthreads();
        {
            constexpr int STAGE = 16384;
            constexpr int KT = 32;
            auto load_stage = [&](int ks) {
                uint32_t sa = sb + OFF + (uint32_t)(ks & 3) * STAGE;
                #pragma unroll
                for (int v = tid; v < 512; v += 128) {
                    int i = v >> 6, inner = v & 63;
                    cp16(sa + (uint32_t)v * 16,
                         g_h1 + ((size_t)(bm1 * 8 + i) * 64 + 2 * ks) * 256 + inner * 8);
                }
                uint32_t sB = sa + 8192;
                #pragma unroll
                for (int v = tid; v < 512; v += 128) {
                    int j = v >> 5, inner = v & 31;
                    cp16(sB + (uint32_t)v * 16,
                         g_W2T + ((size_t)(bn1 * 16 + j) * 64 + 2 * ks) * 128 + inner * 8);
                }
                cp_commit();
            };

            float acc[4][8][4];
            #pragma unroll
            for (int i = 0; i < 4; i++)
                #pragma unroll
                for (int j = 0; j < 8; j++)
                    #pragma unroll
                    for (int q = 0; q < 4; q++) acc[i][j][q] = 0.f;

            load_stage(0); load_stage(1); load_stage(2);
            for (int kt = 0; kt < KT; kt++) {
                int ahead = KT - 1 - kt;
                if (ahead >= 2) cp_wait<2>();
                else if (ahead == 1) cp_wait<1>();
                else cp_wait<0>();
                __syncthreads();
                if (kt + 3 < KT) load_stage(kt + 3);

                uint32_t sa = sb + OFF + (uint32_t)(kt & 3) * STAGE;
                uint32_t sB = sa + 8192;
                #pragma unroll
                for (int kk = 0; kk < 2; kk++) {
                    uint32_t afr[4][4], bfr[8][2];
                    #pragma unroll
                    for (int mf = 0; mf < 4; mf++) {
                        uint32_t ad = sa + (uint32_t)((wm * 4 + mf) * 1024 + kk * 512) + lane * 16;
                        asm volatile("ld.shared.v4.b32 {%0,%1,%2,%3}, [%4];"
                            : "=r"(afr[mf][0]), "=r"(afr[mf][1]), "=r"(afr[mf][2]), "=r"(afr[mf][3])
                            : "r"(ad));
                    }
                    #pragma unroll
                    for (int nf = 0; nf < 8; nf++) {
                        uint32_t bd = sB + (uint32_t)((wn * 8 + nf) * 512 + kk * 256) + lane * 8;
                        asm volatile("ld.shared.v2.b32 {%0,%1}, [%2];"
                            : "=r"(bfr[nf][0]), "=r"(bfr[nf][1]) : "r"(bd));
                    }
                    #pragma unroll
                    for (int mf = 0; mf < 4; mf++)
                        #pragma unroll
                        for (int nf = 0; nf < 8; nf++)
                            mma16(acc[mf][nf], afr[mf], bfr[nf]);
                }
            }

            #pragma unroll
            for (int mf = 0; mf < 4; mf++) {
                int ml = wm * 64 + mf * 16 + r;
                #pragma unroll
                for (int nfp = 0; nfp < 4; nfp++) {
                    uint32_t q[4];
                    #pragma unroll
                    for (int h = 0; h < 2; h++) {
                        int nf = nfp * 2 + h;
                        int nl0 = wn * 64 + nf * 8 + tig * 2;
                        float v00 = acc[mf][nf][0] + hS[128 + nl0];
                        float v01 = acc[mf][nf][1] + hS[128 + nl0 + 1];
                        float v10 = acc[mf][nf][2] + hS[128 + nl0];
                        float v11 = acc[mf][nf][3] + hS[128 + nl0 + 1];
                        v00 = v00 > 0.f ? v00 : 0.f;  v01 = v01 > 0.f ? v01 : 0.f;
                        v10 = v10 > 0.f ? v10 : 0.f;  v11 = v11 > 0.f ? v11 : 0.f;
                        __half2 lo = __floats2half2_rn(v00, v01);
                        __half2 hi = __floats2half2_rn(v10, v11);
                        q[h * 2]     = *(uint32_t*)&lo;
                        q[h * 2 + 1] = *(uint32_t*)&hi;
                    }
                    int mblk = (bm1 * 128 + ml) >> 4;
                    int nblk = (bn1 * 128 + wn * 64 + nfp * 16) >> 4;
                    size_t off = ((size_t)mblk * KOUT + nblk) * 256 + lane * 8;
                    *(uint4*)&g_h2[off] = make_uint4(q[0], q[1], q[2], q[3]);
                }
            }
        }
        __threadfence();
        __syncthreads();
        if (tid == 0) atomicAdd(&g_c2[bm1], 1u);

        // ================= G3 ================= (R14 verbatim)
        if (tid == 0) { spin_ge(&g_c2[bm3 >> 1], 8u * (unsigned)(t + 1)); __threadfence(); }
        __syncthreads();
        if (tid < 64) {
            int m = bm3 * 64 + tid;
            const float* ap = actions + ((size_t)m * T_STEPS + t) * 2;
            hS[832 + tid] = ap[0];
            hS[896 + tid] = ap[1];
        }
        {
            constexpr int STAGE = 8192;
            constexpr int KT = 32;
            auto load_stage = [&](int ks) {
                uint32_t sa = sb + OFF + (uint32_t)(ks & 3) * STAGE;
                #pragma unroll
                for (int v = tid; v < 256; v += 128) {
                    int i = v >> 6, inner = v & 63;
                    cp16(sa + (uint32_t)v * 16,
                         g_h2 + ((size_t)(bm3 * 4 + i) * 64 + 2 * ks) * 256 + inner * 8);
                }
                uint32_t sB = sa + 4096;
                #pragma unroll
                for (int v = tid; v < 256; v += 128) {
                    int j = v >> 5, inner = v & 31;
                    cp16(sB + (uint32_t)v * 16,
                         g_W3T + ((size_t)(bn3 * 8 + j) * 64 + 2 * ks) * 128 + inner * 8);
                }
                cp_commit();
            };

            float acc[2][4][4];
            #pragma unroll
            for (int i = 0; i < 2; i++)
                #pragma unroll
                for (int j = 0; j < 4; j++)
                    #pragma unroll
                    for (int q = 0; q < 4; q++) acc[i][j][q] = 0.f;

            load_stage(0); load_stage(1); load_stage(2);
            for (int kt = 0; kt < KT; kt++) {
                int ahead = KT - 1 - kt;
                if (ahead >= 2) cp_wait<2>();
                else if (ahead == 1) cp_wait<1>();
                else cp_wait<0>();
                __syncthreads();
                if (kt + 3 < KT) load_stage(kt + 3);

                uint32_t sa = sb + OFF + (uint32_t)(kt & 3) * STAGE;
                uint32_t sB = sa + 4096;
                #pragma unroll
                for (int kk = 0; kk < 2; kk++) {
                    uint32_t afr[2][4], bfr[4][2];
                    #pragma unroll
                    for (int mf = 0; mf < 2; mf++) {
                        uint32_t ad = sa + (uint32_t)((wm * 2 + mf) * 1024 + kk * 512) + lane * 16;
                        asm volatile("ld.shared.v4.b32 {%0,%1,%2,%3}, [%4];"
                            : "=r"(afr[mf][0]), "=r"(afr[mf][1]), "=r"(afr[mf][2]), "=r"(afr[mf][3])
                            : "r"(ad));
                    }
                    #pragma unroll
                    for (int nf = 0; nf < 4; nf++) {
                        uint32_t bd = sB + (uint32_t)((wn * 4 + nf) * 512 + kk * 256) + lane * 8;
                        asm volatile("ld.shared.v2.b32 {%0,%1}, [%2];"
                            : "=r"(bfr[nf][0]), "=r"(bfr[nf][1]) : "r"(bd));
                    }
                    #pragma unroll
                    for (int mf = 0; mf < 2; mf++)
                        #pragma unroll
                        for (int nf = 0; nf < 4; nf++)
                            mma16(acc[mf][nf], afr[mf], bfr[nf]);
                }
            }

            #pragma unroll
            for (int mf = 0; mf < 2; mf++) {
                int ml = wm * 32 + mf * 16 + r;
                int m = bm3 * 64 + ml;
                float a0L = hS[832 + ml],     a1L = hS[896 + ml];
                float a0H = hS[832 + ml + 8], a1H = hS[896 + ml + 8];
                #pragma unroll
                for (int nf = 0; nf < 4; nf++) {
                    int nl0 = wn * 32 + nf * 8 + tig * 2;
                    int n = bn3 * 32 + (nl0 >> 1);
                    float p0 = acc[mf][nf][0] + hS[256 + nl0];
                    float p1 = acc[mf][nf][1] + hS[256 + nl0 + 1];
                    float p2 = acc[mf][nf][2] + hS[256 + nl0];
                    float p3 = acc[mf][nf][3] + hS[256 + nl0 + 1];
                    float sv0 = g_s[(size_t)m * NDIM + n];
                    float sv1 = g_s[(size_t)(m + 8) * NDIM + n];
                    float ns0 = fmaf(DT_C, fmaf(p0, a0L, p1 * a1L), sv0);
                    float ns1 = fmaf(DT_C, fmaf(p2, a0H, p3 * a1H), sv1);
                    g_s[(size_t)m * NDIM + n] = ns0;
                    g_s[(size_t)(m + 8) * NDIM + n] = ns1;
                    g_sr[a_idx_h(m, n, NDIM)] = __float2half_rn(ns0);
                    g_sr[a_idx_h(m + 8, n, NDIM)] = __float2half_rn(ns1);
                    out[((size_t)m * (T_STEPS + 1) + t + 1) * NDIM + n] = ns0;
                    out[((size_t)(m + 8) * (T_STEPS + 1) + t + 1) * NDIM + n] = ns1;
                }
            }
        }
        __threadfence();
        __syncthreads();
        if (tid == 0) atomicAdd(&g_c3[bm3], 1u);
    }
}

// ---------------------------------------------------------------------------
extern "C" void kernel_launch(void* const* d_in, const int* in_sizes, int n_in,
                              void* d_out, int out_size) {
    const float* states  = (const float*)d_in[0];
    const float* actions = (const float*)d_in[1];
    const float* W1 = (const float*)d_in[2];
    const float* b1 = (const float*)d_in[3];
    const float* W2 = (const float*)d_in[4];
    const float* b2 = (const float*)d_in[5];
    const float* W3 = (const float*)d_in[6];
    const float* b3 = (const float*)d_in[7];
    float* out = (float*)d_out;

    __half *pw1t, *pw2t, *pw3t;
    cudaGetSymbolAddress((void**)&pw1t, g_W1T);
    cudaGetSymbolAddress((void**)&pw2t, g_W2T);
    cudaGetSymbolAddress((void**)&pw3t, g_W3T);

    const int SMEM = 4096 + 4 * 16384;   // 69632
    cudaFuncSetAttribute((const void*)rollout,
                         cudaFuncAttributeMaxDynamicSharedMemorySize, SMEM);

    init_kernel<<<(BATCH * NDIM + 255) / 256, 256>>>(states, out);
    const int PREP_N = 1024 * 1024 + 256 * 1024 + 1024 * 128;
    prep_all<<<(PREP_N + 255) / 256, 256>>>(W1, W2, W3, pw1t, pw2t, pw3t);

    rollout<<<256, 128, SMEM>>>(b1, b2, b3 + 256, W1, actions, out);
}